// round 15
// baseline (speedup 1.0000x reference)
#include <cuda_runtime.h>
#include <cuda_bf16.h>
#include <cstdint>
#include <cstddef>

typedef unsigned long long ull;

#define T_   2048
#define B_   128
#define IN_  128
#define H_   256
#define G4_  1024
#define OUT_ 64

#define BG_  16   // batch groups
#define NPAIR 8   // batch-group pairs (= clusters)
#define HCN_ 8    // hidden-slice CTAs per cluster
#define BC_  8    // batches per group

// ---- k_rec smem layout (bytes) ----
#define SM_B2SZ   8448
#define SM_B2(c, p) (((c) * 2 + (p)) * SM_B2SZ)
// red: per (chain, mt) block of [2 kh][8 b][20] f32 = 1280 B
#define SM_RED    (4 * SM_B2SZ)
#define SM_REDBLK 1280
#define SM_MBAR   (SM_RED + 16 * SM_REDBLK)      // mbar[c][p] at +((c*2+p)*8)
#define REC_SMEM  (SM_MBAR + 64)

// ---- k_xg smem: 4 bf16 tiles [128][136] + bias[128] f32 ----
#define XS_  136
#define XG_SMEM (4 * 128 * XS_ * 2 + 512)

// ---- k_out smem: W hi/lo [64][264] + r chunk hi/lo [128][72] + bias ----
#define WOS_ 264
#define RCS_ 72
#define OUT2_SMEM (2 * 64 * WOS_ * 2 + 2 * 128 * RCS_ * 2 + 256)

// tx bytes per consumer mbarrier per step: 8 CTAs x 16 warps... = 8 CTAs x 1KB
#define TX_BYTES 8192

// ---------------- device scratch ----------------
__device__ float d_xg[(size_t)T_ * B_ * G4_];    // [t][bg][hc][bb][col]
__device__ float d_rbuf[(size_t)T_ * B_ * H_];   // [t][b][h]

// ---------------- helpers ----------------
__device__ __forceinline__ float rcpa(float x) {
    float r;
    asm("rcp.approx.f32 %0, %1;" : "=f"(r) : "f"(x));
    return r;
}
__device__ __forceinline__ float sigf(float x) { return rcpa(1.0f + __expf(-x)); }
__device__ __forceinline__ float tanhfa(float x) { return 1.0f - 2.0f * rcpa(1.0f + __expf(2.0f * x)); }

__device__ __forceinline__ void mma16816(float* d,
                                         uint32_t a0, uint32_t a1, uint32_t a2, uint32_t a3,
                                         uint32_t b0, uint32_t b1) {
    asm volatile(
        "mma.sync.aligned.m16n8k16.row.col.f32.bf16.bf16.f32 "
        "{%0,%1,%2,%3}, {%4,%5,%6,%7}, {%8,%9}, {%0,%1,%2,%3};"
        : "+f"(d[0]), "+f"(d[1]), "+f"(d[2]), "+f"(d[3])
        : "r"(a0), "r"(a1), "r"(a2), "r"(a3), "r"(b0), "r"(b1));
}

__device__ __forceinline__ void split2(float a, float b, uint32_t& hi, uint32_t& lo) {
    __nv_bfloat16 ha = __float2bfloat16(a), hb = __float2bfloat16(b);
    hi = (uint32_t)__bfloat16_as_ushort(ha) | ((uint32_t)__bfloat16_as_ushort(hb) << 16);
    __nv_bfloat16 la = __float2bfloat16(a - __bfloat162float(ha));
    __nv_bfloat16 lb = __float2bfloat16(b - __bfloat162float(hb));
    lo = (uint32_t)__bfloat16_as_ushort(la) | ((uint32_t)__bfloat16_as_ushort(lb) << 16);
}

__device__ __forceinline__ uint32_t smem_u32(const void* p) {
    uint32_t a;
    asm("{ .reg .u64 t; cvta.to.shared.u64 t, %1; cvt.u32.u64 %0, t; }" : "=r"(a) : "l"(p));
    return a;
}
__device__ __forceinline__ uint32_t mapa_u32(uint32_t addr, uint32_t rank) {
    uint32_t r;
    asm("mapa.shared::cluster.u32 %0, %1, %2;" : "=r"(r) : "r"(addr), "r"(rank));
    return r;
}
__device__ __forceinline__ void st_async64(uint32_t daddr, ull val, uint32_t dmbar) {
    asm volatile(
        "st.async.weak.shared::cluster.mbarrier::complete_tx::bytes.b64 [%0], %1, [%2];"
        :: "r"(daddr), "l"(val), "r"(dmbar) : "memory");
}
#define MBAR_INIT(a, c) asm volatile("mbarrier.init.shared.b64 [%0], %1;" :: "r"(a), "r"(c) : "memory")
#define MBAR_EXPECT(a, tx) asm volatile( \
    "mbarrier.arrive.expect_tx.shared.b64 _, [%0], %1;" :: "r"(a), "r"(tx) : "memory")
#define MBAR_WAIT_CL(a, par) do { \
    asm volatile("{\n\t.reg .pred P;\nWAITC_%=:\n\t" \
                 "mbarrier.try_wait.parity.acquire.cluster.shared::cta.b64 P, [%0], %1;\n\t" \
                 "@!P bra WAITC_%=;\n\t}" :: "r"(a), "r"(par) : "memory"); \
} while (0)
#define BAR_SYNC(id, n) asm volatile("bar.sync %0, %1;" :: "r"(id), "r"(n) : "memory")
#define CLUSTER_SYNC() do { \
    asm volatile("barrier.cluster.arrive.aligned;" ::: "memory"); \
    asm volatile("barrier.cluster.wait.aligned;" ::: "memory"); \
} while (0)

// ---------------- kernel 1: xg = x @ W_ih^T + b_ih + b_hh (HMMA) -----------
__global__ __launch_bounds__(256, 1) void k_xg(const float* __restrict__ x,
                                               const float* __restrict__ W_ih,
                                               const float* __restrict__ b_ih,
                                               const float* __restrict__ b_hh) {
    extern __shared__ char xsm[];
    __nv_bfloat16* xhi = (__nv_bfloat16*)xsm;
    __nv_bfloat16* xlo = xhi + 128 * XS_;
    __nv_bfloat16* whi = xlo + 128 * XS_;
    __nv_bfloat16* wlo = whi + 128 * XS_;
    float* bias = (float*)(wlo + 128 * XS_);

    const int hc = blockIdx.x;
    const int t = blockIdx.y;
    const int u = threadIdx.x;
    const int wid = u >> 5, lane = u & 31;
    const int g = lane >> 2, tg = lane & 3;

    {
        int row = u >> 1, k0 = (u & 1) * 64;
        const float* src = x + ((size_t)t * B_ + row) * IN_ + k0;
#pragma unroll
        for (int kk = 0; kk < 64; kk += 4) {
            float4 v = *(const float4*)(src + kk);
            uint32_t h0, l0, h1, l1;
            split2(v.x, v.y, h0, l0);
            split2(v.z, v.w, h1, l1);
            *(ull*)&xhi[row * XS_ + k0 + kk] = (ull)h0 | ((ull)h1 << 32);
            *(ull*)&xlo[row * XS_ + k0 + kk] = (ull)l0 | ((ull)l1 << 32);
        }
    }
    {
        int col = u >> 1, k0 = (u & 1) * 64;
        int R = (col & 3) * H_ + hc * 32 + (col >> 2);
        const float* src = W_ih + (size_t)R * IN_ + k0;
#pragma unroll
        for (int kk = 0; kk < 64; kk += 4) {
            float4 v = *(const float4*)(src + kk);
            uint32_t h0, l0, h1, l1;
            split2(v.x, v.y, h0, l0);
            split2(v.z, v.w, h1, l1);
            *(ull*)&whi[col * XS_ + k0 + kk] = (ull)h0 | ((ull)h1 << 32);
            *(ull*)&wlo[col * XS_ + k0 + kk] = (ull)l0 | ((ull)l1 << 32);
        }
    }
    if (u < 128) {
        int R = (u & 3) * H_ + hc * 32 + (u >> 2);
        bias[u] = b_ih[R] + b_hh[R];
    }
    __syncthreads();

    const int R0 = wid * 16;
    float acc[16][4];
#pragma unroll
    for (int nt = 0; nt < 16; nt++)
#pragma unroll
        for (int p = 0; p < 4; p++) acc[nt][p] = 0.f;

#pragma unroll
    for (int kt = 0; kt < 8; kt++) {
        uint32_t Ah[4], Al[4];
#pragma unroll
        for (int p = 0; p < 4; p++) {
            int row = R0 + g + (p & 1) * 8;
            int k = kt * 16 + tg * 2 + (p >> 1) * 8;
            Ah[p] = *(const uint32_t*)&xhi[row * XS_ + k];
            Al[p] = *(const uint32_t*)&xlo[row * XS_ + k];
        }
#pragma unroll
        for (int nt = 0; nt < 16; nt++) {
            int ncol = nt * 8 + g;
            int k = kt * 16 + tg * 2;
            uint32_t bh0 = *(const uint32_t*)&whi[ncol * XS_ + k];
            uint32_t bh1 = *(const uint32_t*)&whi[ncol * XS_ + k + 8];
            uint32_t bl0 = *(const uint32_t*)&wlo[ncol * XS_ + k];
            uint32_t bl1 = *(const uint32_t*)&wlo[ncol * XS_ + k + 8];
            mma16816(acc[nt], Ah[0], Ah[1], Ah[2], Ah[3], bh0, bh1);
            mma16816(acc[nt], Ah[0], Ah[1], Ah[2], Ah[3], bl0, bl1);
            mma16816(acc[nt], Al[0], Al[1], Al[2], Al[3], bh0, bh1);
        }
    }

#pragma unroll
    for (int nt = 0; nt < 16; nt++) {
        int col = nt * 8 + tg * 2;
        float bv0 = bias[col], bv1 = bias[col + 1];
        int ra = R0 + g, rb = R0 + g + 8;
        size_t aa = (((size_t)t * BG_ + (ra >> 3)) * HCN_ + hc) * 1024 + (size_t)(ra & 7) * 128 + col;
        size_t ab = (((size_t)t * BG_ + (rb >> 3)) * HCN_ + hc) * 1024 + (size_t)(rb & 7) * 128 + col;
        *(float2*)&d_xg[aa] = make_float2(acc[nt][0] + bv0, acc[nt][1] + bv1);
        *(float2*)&d_xg[ab] = make_float2(acc[nt][2] + bv0, acc[nt][3] + bv1);
    }
}

// ---------------- kernel 2: persistent recurrence, dual-chain, pair-barriers --
// 8 clusters of 8 CTAs, 512 threads. Warp (mt, kh): GEMM over kh K-half of
// M-tile mt, then pair-local bar.sync(64) and in-pair epilogue (lanes 0-15,
// hl = kh*2 + lane/8). NO full-CTA barrier in the t-loop.
__global__ __cluster_dims__(HCN_, 1, 1) __launch_bounds__(512, 1)
void k_rec(const float* __restrict__ W_hh) {
    extern __shared__ char smem[];
    const uint32_t sb = smem_u32(smem);

    const int u = threadIdx.x;
    const int wid = u >> 5;
    const int lane = u & 31;
    const int g = lane >> 2, tg = lane & 3;
    const int pair = blockIdx.x >> 3;
    const int hc = blockIdx.x & 7;

    if (u == 0) {
#pragma unroll
        for (int i = 0; i < 4; i++) {
            MBAR_INIT(sb + SM_MBAR + i * 8, 1);
            MBAR_EXPECT(sb + SM_MBAR + i * 8, TX_BYTES);
        }
    }
    for (int i = u; i < SM_B2SZ / 4; i += 512) {
        ((uint32_t*)(smem + SM_B2(0, 0)))[i] = 0;
        ((uint32_t*)(smem + SM_B2(1, 0)))[i] = 0;
    }

    uint32_t rbase[HCN_];
#pragma unroll
    for (int r = 0; r < HCN_; r++) rbase[r] = mapa_u32(sb, (uint32_t)r);

    const int mt = wid & 7;
    const int kh = wid >> 3;
    const int R0 = mt * 16;

    // W fragments -> registers (kh K-half)
    uint32_t ahi[8][4], alo[8][4];
#pragma unroll
    for (int kt = 0; kt < 8; kt++) {
        int kbase = kh * 128 + kt * 16 + tg * 2;
#pragma unroll
        for (int p = 0; p < 4; p++) {
            int rs = R0 + g + (p & 1) * 8;
            int kk = kbase + (p >> 1) * 8;
            int gate = rs & 3, hw = rs >> 2;
            const float* wp = W_hh + (size_t)(gate * H_ + hc * 32 + hw) * H_ + kk;
            float2 v = *(const float2*)wp;
            split2(v.x, v.y, ahi[kt][p], alo[kt][p]);
        }
    }
    __syncthreads();
    CLUSTER_SYNC();

    // epilogue identity (lanes 0-15 of each warp)
    const int hl = kh * 2 + (lane >> 3);   // 0..3 local hidden in pair
    const int b = lane & 7;                // batch in group
    const int hh = mt * 4 + hl;            // 0..31 hidden within CTA slice
    const bool epk = (lane < 16);
    float cst0 = 0.0f, cst1 = 0.0f;
    const uint32_t kpg = (uint32_t)((hc * 32 + hh) >> 1);  // valid when hl even

    float* redc[2];
    redc[0] = (float*)(smem + SM_RED + (size_t)(0 * 8 + mt) * SM_REDBLK);
    redc[1] = (float*)(smem + SM_RED + (size_t)(8 + mt) * SM_REDBLK);

    const size_t xgo0 = ((size_t)(pair * 2 + 0) * HCN_ + hc) * 1024 + (size_t)b * 128 + (size_t)hh * 4;
    const size_t xgo1 = ((size_t)(pair * 2 + 1) * HCN_ + hc) * 1024 + (size_t)b * 128 + (size_t)hh * 4;

    for (int t = 0; t < T_; t++) {
        const int par = t & 1;
        const uint32_t ph = (uint32_t)(((t - 1) >> 1) & 1);
        const int parw = (t + 1) & 1;
        const size_t xgt = (size_t)t * (BG_ * HCN_ * 1024);

        // xg prefetch for both chains (lanes 0-15)
        float4 xg40 = make_float4(0.f, 0.f, 0.f, 0.f);
        float4 xg41 = xg40;
        if (epk) {
            xg40 = *(const float4*)&d_xg[xgt + xgo0];
            xg41 = *(const float4*)&d_xg[xgt + xgo1];
        }

#pragma unroll
        for (int c = 0; c < 2; c++) {
            // --- wait for all 8 peers' h for this chain ---
            if (t > 0) {
                uint32_t amb = sb + SM_MBAR + (c * 2 + par) * 8;
                MBAR_WAIT_CL(amb, ph);
                if (u == 0) MBAR_EXPECT(amb, TX_BYTES);
            }

            // --- GEMM: 8 kt, 3 accumulator chains ---
            const char* b2B = smem + SM_B2(c, par);
            float dA[4] = {0.f, 0.f, 0.f, 0.f};
            float dB4[4] = {0.f, 0.f, 0.f, 0.f};
            float dC[4] = {0.f, 0.f, 0.f, 0.f};
#pragma unroll
            for (int kt = 0; kt < 8; kt++) {
                int kp0 = kh * 64 + kt * 8;
                ull w0 = *(const ull*)(b2B + ((size_t)g * 132 + kp0 + tg) * 8);
                ull w1 = *(const ull*)(b2B + ((size_t)g * 132 + kp0 + tg + 4) * 8);
                uint32_t bh0 = (uint32_t)w0, bl0 = (uint32_t)(w0 >> 32);
                uint32_t bh1 = (uint32_t)w1, bl1 = (uint32_t)(w1 >> 32);
                mma16816(dA, ahi[kt][0], ahi[kt][1], ahi[kt][2], ahi[kt][3], bh0, bh1);
                mma16816(dB4, ahi[kt][0], ahi[kt][1], ahi[kt][2], ahi[kt][3], bl0, bl1);
                mma16816(dC, alo[kt][0], alo[kt][1], alo[kt][2], alo[kt][3], bh0, bh1);
            }
            // --- partials to pair-private red block: [kh][b][20] ---
            {
                float* rp = redc[c] + kh * 160;
                rp[(tg * 2 + 0) * 20 + g] = dA[0] + dB4[0] + dC[0];
                rp[(tg * 2 + 1) * 20 + g] = dA[1] + dB4[1] + dC[1];
                rp[(tg * 2 + 0) * 20 + g + 8] = dA[2] + dB4[2] + dC[2];
                rp[(tg * 2 + 1) * 20 + g + 8] = dA[3] + dB4[3] + dC[3];
            }
            BAR_SYNC(c * 8 + mt, 64);   // pair-local: both kh warps of this mt

            // --- in-pair epilogue (lanes 0-15): own 2 hidden x 8 b cells ---
            if (epk) {
                const float* ra = redc[c] + b * 20 + hl * 4;
                const float* rb = redc[c] + 160 + b * 20 + hl * 4;
                float4 p0 = *(const float4*)ra;
                float4 p1 = *(const float4*)rb;
                float4 xg = (c == 0) ? xg40 : xg41;
                float iv = sigf(p0.x + p1.x + xg.x);
                float fv = sigf(p0.y + p1.y + xg.y);
                float gv = tanhfa(p0.z + p1.z + xg.z);
                float ov = sigf(p0.w + p1.w + xg.w);
                float cv = (c == 0) ? cst0 : cst1;
                cv = fv * cv + iv * gv;
                if (c == 0) cst0 = cv; else cst1 = cv;
                float hval = ov * tanhfa(cv);

                // publish pair (hh even, hh+1) packed bf16 hi/lo to 8 peers
                __nv_bfloat16 bh = __float2bfloat16(hval);
                __nv_bfloat16 bl = __float2bfloat16(hval - __bfloat162float(bh));
                unsigned hiw = (unsigned)__bfloat16_as_ushort(bh);
                unsigned low = (unsigned)__bfloat16_as_ushort(bl);
                unsigned hin = __shfl_down_sync(0x0000FFFFu, hiw, 8);
                unsigned lon = __shfl_down_sync(0x0000FFFFu, low, 8);
                if (((hl & 1) == 0) && t < T_ - 1) {
                    ull v = (ull)(hiw | (hin << 16)) | ((ull)(low | (lon << 16)) << 32);
                    uint32_t offD = (uint32_t)SM_B2(c, parw) + ((uint32_t)b * 132 + kpg) * 8;
                    uint32_t offM = (uint32_t)SM_MBAR + (uint32_t)(c * 2 + parw) * 8;
#pragma unroll
                    for (int r = 0; r < HCN_; r++)
                        st_async64(rbase[r] + offD, v, rbase[r] + offM);
                }
                d_rbuf[((size_t)t * B_ + (pair * 2 + c) * BC_ + b) * H_ + hc * 32 + hh] = hval;
            }
        }
    }
    CLUSTER_SYNC();
}

// ---------------- kernel 3: out = r_out @ W_out^T + b_out (HMMA) ----------
__global__ __launch_bounds__(256, 1) void k_out(const float* __restrict__ W_out,
                                                const float* __restrict__ b_out,
                                                float* __restrict__ out) {
    extern __shared__ char osm[];
    __nv_bfloat16* wohi = (__nv_bfloat16*)osm;
    __nv_bfloat16* wolo = wohi + 64 * WOS_;
    __nv_bfloat16* rhi = wolo + 64 * WOS_;
    __nv_bfloat16* rlo = rhi + 128 * RCS_;
    float* bias = (float*)(rlo + 128 * RCS_);

    const int t = blockIdx.x;
    const int u = threadIdx.x;
    const int wid = u >> 5, lane = u & 31;
    const int g = lane >> 2, tg = lane & 3;
    const int R0 = wid * 16;

    {
        int col = u >> 2, k0 = (u & 3) * 64;
        const float* src = W_out + (size_t)col * H_ + k0;
#pragma unroll
        for (int kk = 0; kk < 64; kk += 4) {
            float4 v = *(const float4*)(src + kk);
            uint32_t h0, l0, h1, l1;
            split2(v.x, v.y, h0, l0);
            split2(v.z, v.w, h1, l1);
            *(ull*)&wohi[col * WOS_ + k0 + kk] = (ull)h0 | ((ull)h1 << 32);
            *(ull*)&wolo[col * WOS_ + k0 + kk] = (ull)l0 | ((ull)l1 << 32);
        }
    }
    if (u < 64) bias[u] = b_out[u];

    float acc[8][4];
#pragma unroll
    for (int nt = 0; nt < 8; nt++)
#pragma unroll
        for (int p = 0; p < 4; p++) acc[nt][p] = 0.f;

    for (int kc = 0; kc < 4; kc++) {
        __syncthreads();
        {
            int row = u >> 1, k0 = (u & 1) * 32;
            const float* src = d_rbuf + ((size_t)t * B_ + row) * H_ + kc * 64 + k0;
#pragma unroll
            for (int kk = 0; kk < 32; kk += 4) {
                float4 v = *(const float4*)(src + kk);
                uint32_t h0, l0, h1, l1;
                split2(v.x, v.y, h0, l0);
                split2(v.z, v.w, h1, l1);
                *(ull*)&rhi[row * RCS_ + k0 + kk] = (ull)h0 | ((ull)h1 << 32);
                *(ull*)&rlo[row * RCS_ + k0 + kk] = (ull)l0 | ((ull)l1 << 32);
            }
        }
        __syncthreads();
#pragma unroll
        for (int kt = 0; kt < 4; kt++) {
            uint32_t Ah[4], Al[4];
#pragma unroll
            for (int p = 0; p < 4; p++) {
                int row = R0 + g + (p & 1) * 8;
                int k = kt * 16 + tg * 2 + (p >> 1) * 8;
                Ah[p] = *(const uint32_t*)&rhi[row * RCS_ + k];
                Al[p] = *(const uint32_t*)&rlo[row * RCS_ + k];
            }
#pragma unroll
            for (int nt = 0; nt < 8; nt++) {
                int ncol = nt * 8 + g;
                int k = kc * 64 + kt * 16 + tg * 2;
                uint32_t bh0 = *(const uint32_t*)&wohi[ncol * WOS_ + k];
                uint32_t bh1 = *(const uint32_t*)&wohi[ncol * WOS_ + k + 8];
                uint32_t bl0 = *(const uint32_t*)&wolo[ncol * WOS_ + k];
                uint32_t bl1 = *(const uint32_t*)&wolo[ncol * WOS_ + k + 8];
                mma16816(acc[nt], Ah[0], Ah[1], Ah[2], Ah[3], bh0, bh1);
                mma16816(acc[nt], Ah[0], Ah[1], Ah[2], Ah[3], bl0, bl1);
                mma16816(acc[nt], Al[0], Al[1], Al[2], Al[3], bh0, bh1);
            }
        }
    }

#pragma unroll
    for (int nt = 0; nt < 8; nt++) {
        int col = nt * 8 + tg * 2;
        float bv0 = bias[col], bv1 = bias[col + 1];
        int ra = R0 + g, rb = R0 + g + 8;
        *(float2*)&out[((size_t)t * B_ + ra) * OUT_ + col] =
            make_float2(acc[nt][0] + bv0, acc[nt][1] + bv1);
        *(float2*)&out[((size_t)t * B_ + rb) * OUT_ + col] =
            make_float2(acc[nt][2] + bv0, acc[nt][3] + bv1);
    }
}

// ---------------- launcher ----------------
extern "C" void kernel_launch(void* const* d_in, const int* in_sizes, int n_in,
                              void* d_out, int out_size) {
    const float* x     = (const float*)d_in[0];
    const float* W_ih  = (const float*)d_in[1];
    const float* W_hh  = (const float*)d_in[2];
    const float* b_ih  = (const float*)d_in[3];
    const float* b_hh  = (const float*)d_in[4];
    const float* W_out = (const float*)d_in[5];
    const float* b_out = (const float*)d_in[6];
    float* out = (float*)d_out;

    cudaFuncSetAttribute(k_xg, cudaFuncAttributeMaxDynamicSharedMemorySize, XG_SMEM);
    cudaFuncSetAttribute(k_rec, cudaFuncAttributeMaxDynamicSharedMemorySize, REC_SMEM);
    cudaFuncSetAttribute(k_out, cudaFuncAttributeMaxDynamicSharedMemorySize, OUT2_SMEM);

    k_xg<<<dim3(HCN_, T_), 256, XG_SMEM>>>(x, W_ih, b_ih, b_hh);
    k_rec<<<NPAIR * HCN_, 512, REC_SMEM>>>(W_hh);
    k_out<<<T_, 256, OUT2_SMEM>>>(W_out, b_out, out);
}

// round 16
// speedup vs baseline: 1.2808x; 1.2808x over previous
#include <cuda_runtime.h>
#include <cuda_bf16.h>
#include <cstdint>
#include <cstddef>

typedef unsigned long long ull;

#define T_   2048
#define B_   128
#define IN_  128
#define H_   256
#define G4_  1024
#define OUT_ 64

#define BG_  16   // batch groups
#define NPAIR 8   // batch-group pairs (= clusters)
#define HCN_ 8    // hidden-slice CTAs per cluster
#define BC_  8    // batches per group

// ---- k_rec smem layout (bytes) ----
#define SM_B2SZ   8448
#define SM_B2(c, p) (((c) * 2 + (p)) * SM_B2SZ)
#define SM_REDSZ  8448                       // [2 kh][8 b][132] f32
#define SM_RED(c) (4 * SM_B2SZ + (c) * SM_REDSZ)
#define SM_MBAR   (4 * SM_B2SZ + 2 * SM_REDSZ)   // mbar[c][p] at +((c*2+p)*8)
#define REC_SMEM  (SM_MBAR + 64)

// ---- k_xg smem: 4 bf16 tiles [128][136] + bias[128] f32 ----
#define XS_  136
#define XG_SMEM (4 * 128 * XS_ * 2 + 512)

// ---- k_out smem: W hi/lo [64][264] + r chunk hi/lo [128][72] + bias ----
#define WOS_ 264
#define RCS_ 72
#define OUT2_SMEM (2 * 64 * WOS_ * 2 + 2 * 128 * RCS_ * 2 + 256)

// tx bytes per consumer mbarrier per step: 8 CTAs x 128 pair-lanes x 8 B
#define TX_BYTES 8192

// ---------------- device scratch ----------------
__device__ float d_xg[(size_t)T_ * B_ * G4_];    // [t][bg][hc][bb][col]
__device__ float d_rbuf[(size_t)T_ * B_ * H_];   // [t][b][h]

// ---------------- helpers ----------------
__device__ __forceinline__ float rcpa(float x) {
    float r;
    asm("rcp.approx.f32 %0, %1;" : "=f"(r) : "f"(x));
    return r;
}
__device__ __forceinline__ float sigf(float x) { return rcpa(1.0f + __expf(-x)); }
__device__ __forceinline__ float tanhfa(float x) { return 1.0f - 2.0f * rcpa(1.0f + __expf(2.0f * x)); }

__device__ __forceinline__ void mma16816(float* d,
                                         uint32_t a0, uint32_t a1, uint32_t a2, uint32_t a3,
                                         uint32_t b0, uint32_t b1) {
    asm volatile(
        "mma.sync.aligned.m16n8k16.row.col.f32.bf16.bf16.f32 "
        "{%0,%1,%2,%3}, {%4,%5,%6,%7}, {%8,%9}, {%0,%1,%2,%3};"
        : "+f"(d[0]), "+f"(d[1]), "+f"(d[2]), "+f"(d[3])
        : "r"(a0), "r"(a1), "r"(a2), "r"(a3), "r"(b0), "r"(b1));
}

__device__ __forceinline__ void split2(float a, float b, uint32_t& hi, uint32_t& lo) {
    __nv_bfloat16 ha = __float2bfloat16(a), hb = __float2bfloat16(b);
    hi = (uint32_t)__bfloat16_as_ushort(ha) | ((uint32_t)__bfloat16_as_ushort(hb) << 16);
    __nv_bfloat16 la = __float2bfloat16(a - __bfloat162float(ha));
    __nv_bfloat16 lb = __float2bfloat16(b - __bfloat162float(hb));
    lo = (uint32_t)__bfloat16_as_ushort(la) | ((uint32_t)__bfloat16_as_ushort(lb) << 16);
}

__device__ __forceinline__ uint32_t smem_u32(const void* p) {
    uint32_t a;
    asm("{ .reg .u64 t; cvta.to.shared.u64 t, %1; cvt.u32.u64 %0, t; }" : "=r"(a) : "l"(p));
    return a;
}
__device__ __forceinline__ uint32_t mapa_u32(uint32_t addr, uint32_t rank) {
    uint32_t r;
    asm("mapa.shared::cluster.u32 %0, %1, %2;" : "=r"(r) : "r"(addr), "r"(rank));
    return r;
}
__device__ __forceinline__ void st_async64(uint32_t daddr, ull val, uint32_t dmbar) {
    asm volatile(
        "st.async.weak.shared::cluster.mbarrier::complete_tx::bytes.b64 [%0], %1, [%2];"
        :: "r"(daddr), "l"(val), "r"(dmbar) : "memory");
}
#define MBAR_INIT(a, c) asm volatile("mbarrier.init.shared.b64 [%0], %1;" :: "r"(a), "r"(c) : "memory")
#define MBAR_EXPECT(a, tx) asm volatile( \
    "mbarrier.arrive.expect_tx.shared.b64 _, [%0], %1;" :: "r"(a), "r"(tx) : "memory")
#define MBAR_WAIT_CL(a, par) do { \
    asm volatile("{\n\t.reg .pred P;\nWAITC_%=:\n\t" \
                 "mbarrier.try_wait.parity.acquire.cluster.shared::cta.b64 P, [%0], %1;\n\t" \
                 "@!P bra WAITC_%=;\n\t}" :: "r"(a), "r"(par) : "memory"); \
} while (0)
#define CLUSTER_SYNC() do { \
    asm volatile("barrier.cluster.arrive.aligned;" ::: "memory"); \
    asm volatile("barrier.cluster.wait.aligned;" ::: "memory"); \
} while (0)

// ---------------- kernel 1: xg = x @ W_ih^T + b_ih + b_hh (HMMA) -----------
__global__ __launch_bounds__(256, 1) void k_xg(const float* __restrict__ x,
                                               const float* __restrict__ W_ih,
                                               const float* __restrict__ b_ih,
                                               const float* __restrict__ b_hh) {
    extern __shared__ char xsm[];
    __nv_bfloat16* xhi = (__nv_bfloat16*)xsm;
    __nv_bfloat16* xlo = xhi + 128 * XS_;
    __nv_bfloat16* whi = xlo + 128 * XS_;
    __nv_bfloat16* wlo = whi + 128 * XS_;
    float* bias = (float*)(wlo + 128 * XS_);

    const int hc = blockIdx.x;
    const int t = blockIdx.y;
    const int u = threadIdx.x;
    const int wid = u >> 5, lane = u & 31;
    const int g = lane >> 2, tg = lane & 3;

    {
        int row = u >> 1, k0 = (u & 1) * 64;
        const float* src = x + ((size_t)t * B_ + row) * IN_ + k0;
#pragma unroll
        for (int kk = 0; kk < 64; kk += 4) {
            float4 v = *(const float4*)(src + kk);
            uint32_t h0, l0, h1, l1;
            split2(v.x, v.y, h0, l0);
            split2(v.z, v.w, h1, l1);
            *(ull*)&xhi[row * XS_ + k0 + kk] = (ull)h0 | ((ull)h1 << 32);
            *(ull*)&xlo[row * XS_ + k0 + kk] = (ull)l0 | ((ull)l1 << 32);
        }
    }
    {
        int col = u >> 1, k0 = (u & 1) * 64;
        int R = (col & 3) * H_ + hc * 32 + (col >> 2);
        const float* src = W_ih + (size_t)R * IN_ + k0;
#pragma unroll
        for (int kk = 0; kk < 64; kk += 4) {
            float4 v = *(const float4*)(src + kk);
            uint32_t h0, l0, h1, l1;
            split2(v.x, v.y, h0, l0);
            split2(v.z, v.w, h1, l1);
            *(ull*)&whi[col * XS_ + k0 + kk] = (ull)h0 | ((ull)h1 << 32);
            *(ull*)&wlo[col * XS_ + k0 + kk] = (ull)l0 | ((ull)l1 << 32);
        }
    }
    if (u < 128) {
        int R = (u & 3) * H_ + hc * 32 + (u >> 2);
        bias[u] = b_ih[R] + b_hh[R];
    }
    __syncthreads();

    const int R0 = wid * 16;
    float acc[16][4];
#pragma unroll
    for (int nt = 0; nt < 16; nt++)
#pragma unroll
        for (int p = 0; p < 4; p++) acc[nt][p] = 0.f;

#pragma unroll
    for (int kt = 0; kt < 8; kt++) {
        uint32_t Ah[4], Al[4];
#pragma unroll
        for (int p = 0; p < 4; p++) {
            int row = R0 + g + (p & 1) * 8;
            int k = kt * 16 + tg * 2 + (p >> 1) * 8;
            Ah[p] = *(const uint32_t*)&xhi[row * XS_ + k];
            Al[p] = *(const uint32_t*)&xlo[row * XS_ + k];
        }
#pragma unroll
        for (int nt = 0; nt < 16; nt++) {
            int ncol = nt * 8 + g;
            int k = kt * 16 + tg * 2;
            uint32_t bh0 = *(const uint32_t*)&whi[ncol * XS_ + k];
            uint32_t bh1 = *(const uint32_t*)&whi[ncol * XS_ + k + 8];
            uint32_t bl0 = *(const uint32_t*)&wlo[ncol * XS_ + k];
            uint32_t bl1 = *(const uint32_t*)&wlo[ncol * XS_ + k + 8];
            mma16816(acc[nt], Ah[0], Ah[1], Ah[2], Ah[3], bh0, bh1);
            mma16816(acc[nt], Ah[0], Ah[1], Ah[2], Ah[3], bl0, bl1);
            mma16816(acc[nt], Al[0], Al[1], Al[2], Al[3], bh0, bh1);
        }
    }

#pragma unroll
    for (int nt = 0; nt < 16; nt++) {
        int col = nt * 8 + tg * 2;
        float bv0 = bias[col], bv1 = bias[col + 1];
        int ra = R0 + g, rb = R0 + g + 8;
        size_t aa = (((size_t)t * BG_ + (ra >> 3)) * HCN_ + hc) * 1024 + (size_t)(ra & 7) * 128 + col;
        size_t ab = (((size_t)t * BG_ + (rb >> 3)) * HCN_ + hc) * 1024 + (size_t)(rb & 7) * 128 + col;
        *(float2*)&d_xg[aa] = make_float2(acc[nt][0] + bv0, acc[nt][1] + bv1);
        *(float2*)&d_xg[ab] = make_float2(acc[nt][2] + bv0, acc[nt][3] + bv1);
    }
}

// ---------------- kernel 2: persistent recurrence, dual-chain ----------------
// R14 structure (measured 5283us) with ONE change: epilogue+publish for chain 0
// moved to right after sync1, BEFORE chain 1's wait+GEMM, so chain 0's DSMEM
// messages get gemm1's duration (~450cyc) of free flight time.
__global__ __cluster_dims__(HCN_, 1, 1) __launch_bounds__(512, 1)
void k_rec(const float* __restrict__ W_hh) {
    extern __shared__ char smem[];
    const uint32_t sb = smem_u32(smem);

    const int u = threadIdx.x;
    const int wid = u >> 5;
    const int lane = u & 31;
    const int g = lane >> 2, tg = lane & 3;
    const int pair = blockIdx.x >> 3;
    const int hc = blockIdx.x & 7;

    if (u == 0) {
#pragma unroll
        for (int i = 0; i < 4; i++) {
            MBAR_INIT(sb + SM_MBAR + i * 8, 1);
            MBAR_EXPECT(sb + SM_MBAR + i * 8, TX_BYTES);
        }
    }
    for (int i = u; i < SM_B2SZ / 4; i += 512) {
        ((uint32_t*)(smem + SM_B2(0, 0)))[i] = 0;
        ((uint32_t*)(smem + SM_B2(1, 0)))[i] = 0;
    }

    uint32_t rbase[HCN_];
#pragma unroll
    for (int r = 0; r < HCN_; r++) rbase[r] = mapa_u32(sb, (uint32_t)r);

    const int mt = wid & 7;
    const int kh = wid >> 3;
    const int R0 = mt * 16;

    uint32_t ahi[8][4], alo[8][4];
#pragma unroll
    for (int kt = 0; kt < 8; kt++) {
        int kbase = kh * 128 + kt * 16 + tg * 2;
#pragma unroll
        for (int p = 0; p < 4; p++) {
            int rs = R0 + g + (p & 1) * 8;
            int kk = kbase + (p >> 1) * 8;
            int gate = rs & 3, hw = rs >> 2;
            const float* wp = W_hh + (size_t)(gate * H_ + hc * 32 + hw) * H_ + kk;
            float2 v = *(const float2*)wp;
            split2(v.x, v.y, ahi[kt][p], alo[kt][p]);
        }
    }
    __syncthreads();
    CLUSTER_SYNC();

    const int bb = wid - 8;
    const int hh = lane;
    float c0s = 0.0f, c1s = 0.0f;
    const size_t xgb0 = ((size_t)(pair * 2 + 0) * HCN_ + hc) * 1024
                      + (size_t)(wid >= 8 ? bb : 0) * 128 + (size_t)hh * 4;
    const size_t xgb1 = ((size_t)(pair * 2 + 1) * HCN_ + hc) * 1024
                      + (size_t)(wid >= 8 ? bb : 0) * 128 + (size_t)hh * 4;
    const uint32_t kpg = (uint32_t)((hc * 32 + hh) >> 1);

    float* red0 = (float*)(smem + SM_RED(0));
    float* red1 = (float*)(smem + SM_RED(1));

    for (int t = 0; t < T_; t++) {
        const int par = t & 1;
        const uint32_t ph = (uint32_t)(((t - 1) >> 1) & 1);
        const int parw = (t + 1) & 1;
        const size_t xgt = (size_t)t * (BG_ * HCN_ * 1024);

        float4 xg40 = make_float4(0.f, 0.f, 0.f, 0.f);
        float4 xg41 = xg40;
        if (wid >= 8) {
            xg40 = *(const float4*)&d_xg[xgt + xgb0];
            xg41 = *(const float4*)&d_xg[xgt + xgb1];
        }

        // ================= chain 0: wait + GEMM =================
        if (t > 0) {
            uint32_t amb = sb + SM_MBAR + (0 * 2 + par) * 8;
            MBAR_WAIT_CL(amb, ph);
            if (u == 0) MBAR_EXPECT(amb, TX_BYTES);
        }
        {
            const char* b2B = smem + SM_B2(0, par);
            float dA[4] = {0.f, 0.f, 0.f, 0.f};
            float dB4[4] = {0.f, 0.f, 0.f, 0.f};
            float dC[4] = {0.f, 0.f, 0.f, 0.f};
#pragma unroll
            for (int kt = 0; kt < 8; kt++) {
                int kp0 = kh * 64 + kt * 8;
                ull w0 = *(const ull*)(b2B + ((size_t)g * 132 + kp0 + tg) * 8);
                ull w1 = *(const ull*)(b2B + ((size_t)g * 132 + kp0 + tg + 4) * 8);
                uint32_t bh0 = (uint32_t)w0, bl0 = (uint32_t)(w0 >> 32);
                uint32_t bh1 = (uint32_t)w1, bl1 = (uint32_t)(w1 >> 32);
                mma16816(dA, ahi[kt][0], ahi[kt][1], ahi[kt][2], ahi[kt][3], bh0, bh1);
                mma16816(dB4, ahi[kt][0], ahi[kt][1], ahi[kt][2], ahi[kt][3], bl0, bl1);
                mma16816(dC, alo[kt][0], alo[kt][1], alo[kt][2], alo[kt][3], bh0, bh1);
            }
            float* rp = &red0[(size_t)(kh * 8) * 132];
            rp[(tg * 2 + 0) * 132 + R0 + g] = dA[0] + dB4[0] + dC[0];
            rp[(tg * 2 + 1) * 132 + R0 + g] = dA[1] + dB4[1] + dC[1];
            rp[(tg * 2 + 0) * 132 + R0 + g + 8] = dA[2] + dB4[2] + dC[2];
            rp[(tg * 2 + 1) * 132 + R0 + g + 8] = dA[3] + dB4[3] + dC[3];
        }
        __syncthreads();   // sync1: red0 complete

        // ======== epilogue chain 0 (warps 8-15) — publish EARLY ========
        if (wid >= 8) {
            float4 p0 = *(const float4*)&red0[(size_t)bb * 132 + hh * 4];
            float4 p1 = *(const float4*)&red0[(size_t)(8 + bb) * 132 + hh * 4];
            float iv = sigf(p0.x + p1.x + xg40.x);
            float fv = sigf(p0.y + p1.y + xg40.y);
            float gv = tanhfa(p0.z + p1.z + xg40.z);
            float ov = sigf(p0.w + p1.w + xg40.w);
            c0s = fv * c0s + iv * gv;
            float hval = ov * tanhfa(c0s);

            __nv_bfloat16 bh = __float2bfloat16(hval);
            __nv_bfloat16 bl = __float2bfloat16(hval - __bfloat162float(bh));
            unsigned hiw = (unsigned)__bfloat16_as_ushort(bh);
            unsigned low = (unsigned)__bfloat16_as_ushort(bl);
            unsigned hin = __shfl_down_sync(0xFFFFFFFFu, hiw, 1);
            unsigned lon = __shfl_down_sync(0xFFFFFFFFu, low, 1);
            if (((lane & 1) == 0) && t < T_ - 1) {
                ull v = (ull)(hiw | (hin << 16)) | ((ull)(low | (lon << 16)) << 32);
                uint32_t offD = (uint32_t)SM_B2(0, parw) + ((uint32_t)bb * 132 + kpg) * 8;
                uint32_t offM = (uint32_t)SM_MBAR + (uint32_t)(0 * 2 + parw) * 8;
#pragma unroll
                for (int r = 0; r < HCN_; r++)
                    st_async64(rbase[r] + offD, v, rbase[r] + offM);
            }
            d_rbuf[((size_t)t * B_ + (pair * 2 + 0) * BC_ + bb) * H_ + hc * 32 + hh] = hval;
        }

        // ================= chain 1: wait + GEMM =================
        if (t > 0) {
            uint32_t amb = sb + SM_MBAR + (1 * 2 + par) * 8;
            MBAR_WAIT_CL(amb, ph);
            if (u == 0) MBAR_EXPECT(amb, TX_BYTES);
        }
        {
            const char* b2B = smem + SM_B2(1, par);
            float dA[4] = {0.f, 0.f, 0.f, 0.f};
            float dB4[4] = {0.f, 0.f, 0.f, 0.f};
            float dC[4] = {0.f, 0.f, 0.f, 0.f};
#pragma unroll
            for (int kt = 0; kt < 8; kt++) {
                int kp0 = kh * 64 + kt * 8;
                ull w0 = *(const ull*)(b2B + ((size_t)g * 132 + kp0 + tg) * 8);
                ull w1 = *(const ull*)(b2B + ((size_t)g * 132 + kp0 + tg + 4) * 8);
                uint32_t bh0 = (uint32_t)w0, bl0 = (uint32_t)(w0 >> 32);
                uint32_t bh1 = (uint32_t)w1, bl1 = (uint32_t)(w1 >> 32);
                mma16816(dA, ahi[kt][0], ahi[kt][1], ahi[kt][2], ahi[kt][3], bh0, bh1);
                mma16816(dB4, ahi[kt][0], ahi[kt][1], ahi[kt][2], ahi[kt][3], bl0, bl1);
                mma16816(dC, alo[kt][0], alo[kt][1], alo[kt][2], alo[kt][3], bh0, bh1);
            }
            float* rp = &red1[(size_t)(kh * 8) * 132];
            rp[(tg * 2 + 0) * 132 + R0 + g] = dA[0] + dB4[0] + dC[0];
            rp[(tg * 2 + 1) * 132 + R0 + g] = dA[1] + dB4[1] + dC[1];
            rp[(tg * 2 + 0) * 132 + R0 + g + 8] = dA[2] + dB4[2] + dC[2];
            rp[(tg * 2 + 1) * 132 + R0 + g + 8] = dA[3] + dB4[3] + dC[3];
        }
        __syncthreads();   // sync2: red1 complete (and epi0's red0 reads done)

        // --- epilogue chain 1 (warps 8-15) ---
        if (wid >= 8) {
            float4 p0 = *(const float4*)&red1[(size_t)bb * 132 + hh * 4];
            float4 p1 = *(const float4*)&red1[(size_t)(8 + bb) * 132 + hh * 4];
            float iv = sigf(p0.x + p1.x + xg41.x);
            float fv = sigf(p0.y + p1.y + xg41.y);
            float gv = tanhfa(p0.z + p1.z + xg41.z);
            float ov = sigf(p0.w + p1.w + xg41.w);
            c1s = fv * c1s + iv * gv;
            float hval = ov * tanhfa(c1s);

            __nv_bfloat16 bh = __float2bfloat16(hval);
            __nv_bfloat16 bl = __float2bfloat16(hval - __bfloat162float(bh));
            unsigned hiw = (unsigned)__bfloat16_as_ushort(bh);
            unsigned low = (unsigned)__bfloat16_as_ushort(bl);
            unsigned hin = __shfl_down_sync(0xFFFFFFFFu, hiw, 1);
            unsigned lon = __shfl_down_sync(0xFFFFFFFFu, low, 1);
            if (((lane & 1) == 0) && t < T_ - 1) {
                ull v = (ull)(hiw | (hin << 16)) | ((ull)(low | (lon << 16)) << 32);
                uint32_t offD = (uint32_t)SM_B2(1, parw) + ((uint32_t)bb * 132 + kpg) * 8;
                uint32_t offM = (uint32_t)SM_MBAR + (uint32_t)(1 * 2 + parw) * 8;
#pragma unroll
                for (int r = 0; r < HCN_; r++)
                    st_async64(rbase[r] + offD, v, rbase[r] + offM);
            }
            d_rbuf[((size_t)t * B_ + (pair * 2 + 1) * BC_ + bb) * H_ + hc * 32 + hh] = hval;
        }
    }
    CLUSTER_SYNC();
}

// ---------------- kernel 3: out = r_out @ W_out^T + b_out (HMMA) ----------
__global__ __launch_bounds__(256, 1) void k_out(const float* __restrict__ W_out,
                                                const float* __restrict__ b_out,
                                                float* __restrict__ out) {
    extern __shared__ char osm[];
    __nv_bfloat16* wohi = (__nv_bfloat16*)osm;
    __nv_bfloat16* wolo = wohi + 64 * WOS_;
    __nv_bfloat16* rhi = wolo + 64 * WOS_;
    __nv_bfloat16* rlo = rhi + 128 * RCS_;
    float* bias = (float*)(rlo + 128 * RCS_);

    const int t = blockIdx.x;
    const int u = threadIdx.x;
    const int wid = u >> 5, lane = u & 31;
    const int g = lane >> 2, tg = lane & 3;
    const int R0 = wid * 16;

    {
        int col = u >> 2, k0 = (u & 3) * 64;
        const float* src = W_out + (size_t)col * H_ + k0;
#pragma unroll
        for (int kk = 0; kk < 64; kk += 4) {
            float4 v = *(const float4*)(src + kk);
            uint32_t h0, l0, h1, l1;
            split2(v.x, v.y, h0, l0);
            split2(v.z, v.w, h1, l1);
            *(ull*)&wohi[col * WOS_ + k0 + kk] = (ull)h0 | ((ull)h1 << 32);
            *(ull*)&wolo[col * WOS_ + k0 + kk] = (ull)l0 | ((ull)l1 << 32);
        }
    }
    if (u < 64) bias[u] = b_out[u];

    float acc[8][4];
#pragma unroll
    for (int nt = 0; nt < 8; nt++)
#pragma unroll
        for (int p = 0; p < 4; p++) acc[nt][p] = 0.f;

    for (int kc = 0; kc < 4; kc++) {
        __syncthreads();
        {
            int row = u >> 1, k0 = (u & 1) * 32;
            const float* src = d_rbuf + ((size_t)t * B_ + row) * H_ + kc * 64 + k0;
#pragma unroll
            for (int kk = 0; kk < 32; kk += 4) {
                float4 v = *(const float4*)(src + kk);
                uint32_t h0, l0, h1, l1;
                split2(v.x, v.y, h0, l0);
                split2(v.z, v.w, h1, l1);
                *(ull*)&rhi[row * RCS_ + k0 + kk] = (ull)h0 | ((ull)h1 << 32);
                *(ull*)&rlo[row * RCS_ + k0 + kk] = (ull)l0 | ((ull)l1 << 32);
            }
        }
        __syncthreads();
#pragma unroll
        for (int kt = 0; kt < 4; kt++) {
            uint32_t Ah[4], Al[4];
#pragma unroll
            for (int p = 0; p < 4; p++) {
                int row = R0 + g + (p & 1) * 8;
                int k = kt * 16 + tg * 2 + (p >> 1) * 8;
                Ah[p] = *(const uint32_t*)&rhi[row * RCS_ + k];
                Al[p] = *(const uint32_t*)&rlo[row * RCS_ + k];
            }
#pragma unroll
            for (int nt = 0; nt < 8; nt++) {
                int ncol = nt * 8 + g;
                int k = kc * 64 + kt * 16 + tg * 2;
                uint32_t bh0 = *(const uint32_t*)&wohi[ncol * WOS_ + k];
                uint32_t bh1 = *(const uint32_t*)&wohi[ncol * WOS_ + k + 8];
                uint32_t bl0 = *(const uint32_t*)&wolo[ncol * WOS_ + k];
                uint32_t bl1 = *(const uint32_t*)&wolo[ncol * WOS_ + k + 8];
                mma16816(acc[nt], Ah[0], Ah[1], Ah[2], Ah[3], bh0, bh1);
                mma16816(acc[nt], Ah[0], Ah[1], Ah[2], Ah[3], bl0, bl1);
                mma16816(acc[nt], Al[0], Al[1], Al[2], Al[3], bh0, bh1);
            }
        }
    }

#pragma unroll
    for (int nt = 0; nt < 8; nt++) {
        int col = nt * 8 + tg * 2;
        float bv0 = bias[col], bv1 = bias[col + 1];
        int ra = R0 + g, rb = R0 + g + 8;
        *(float2*)&out[((size_t)t * B_ + ra) * OUT_ + col] =
            make_float2(acc[nt][0] + bv0, acc[nt][1] + bv1);
        *(float2*)&out[((size_t)t * B_ + rb) * OUT_ + col] =
            make_float2(acc[nt][2] + bv0, acc[nt][3] + bv1);
    }
}

// ---------------- launcher ----------------
extern "C" void kernel_launch(void* const* d_in, const int* in_sizes, int n_in,
                              void* d_out, int out_size) {
    const float* x     = (const float*)d_in[0];
    const float* W_ih  = (const float*)d_in[1];
    const float* W_hh  = (const float*)d_in[2];
    const float* b_ih  = (const float*)d_in[3];
    const float* b_hh  = (const float*)d_in[4];
    const float* W_out = (const float*)d_in[5];
    const float* b_out = (const float*)d_in[6];
    float* out = (float*)d_out;

    cudaFuncSetAttribute(k_xg, cudaFuncAttributeMaxDynamicSharedMemorySize, XG_SMEM);
    cudaFuncSetAttribute(k_rec, cudaFuncAttributeMaxDynamicSharedMemorySize, REC_SMEM);
    cudaFuncSetAttribute(k_out, cudaFuncAttributeMaxDynamicSharedMemorySize, OUT2_SMEM);

    k_xg<<<dim3(HCN_, T_), 256, XG_SMEM>>>(x, W_ih, b_ih, b_hh);
    k_rec<<<NPAIR * HCN_, 512, REC_SMEM>>>(W_hh);
    k_out<<<T_, 256, OUT2_SMEM>>>(W_out, b_out, out);
}